// round 17
// baseline (speedup 1.0000x reference)
#include <cuda_runtime.h>
#include <cuda_bf16.h>
#include <cstdint>

// ---------------- problem constants ----------------
#define NV      50000      // nodes
#define NE      200000     // edges
#define NB      1024       // graphs
#define DD      24         // node feature dim
#define EF      8          // edge feature dim
#define EH      128        // edge MLP hidden
#define DW      576        // D*D
#define MT      1563       // m-tiles of 128 edges
#define ME_PAD  (MT*128)   // 200064 padded edge rows
#define BN      96         // n per CTA
#define CPB     24         // CTAs (strips) per bn
#define NTILE   66         // tiles per CTA (ceil(1563/24))
#define GEMM_CTAS (6*CPB)  // 144

// ---------------- device scratch (zero-init at module load) ----------------
__device__ __align__(16) __nv_bfloat16 g_Hhi[(size_t)ME_PAD * EH];  // 51.2 MB
__device__ __align__(16) __nv_bfloat16 g_Hlo[(size_t)ME_PAD * EH];  // 51.2 MB
__device__ __align__(16) __nv_bfloat16 g_Bhi[EH * DW];              // 144 KB
__device__ __align__(16) __nv_bfloat16 g_Blo[EH * DW];              // 144 KB
__device__ float g_We[(size_t)ME_PAD * DW];    // 461 MB per-edge 24x24 weights
__device__ float g_agg[NV * DD];
__device__ float g_cnt[NV];
__device__ float g_x1[NV * DD];
__device__ float g_x2[NV * DD];
__device__ int   g_start[NB + 1];
__device__ float g_qstar[NB * 2 * DD];
__device__ float g_h[NB * DD];
__device__ float g_c[NB * DD];

// ---------------- zero + W2 bf16-split conversion (fused) ----------------
__global__ void zero_all_kernel(const float* __restrict__ w_e2) {
    int i = blockIdx.x * blockDim.x + threadIdx.x;
    int stride = gridDim.x * blockDim.x;
    for (int k = i; k < NV * DD; k += stride) g_agg[k] = 0.f;
    for (int k = i; k < NV; k += stride) g_cnt[k] = 0.f;
    for (int k = i; k < NB * 2 * DD; k += stride) g_qstar[k] = 0.f;
    for (int k = i; k < NB * DD; k += stride) { g_h[k] = 0.f; g_c[k] = 0.f; }
    for (int k = i; k < EH * DW; k += stride) {
        float v = w_e2[k];
        __nv_bfloat16 hi = __float2bfloat16(v);
        g_Bhi[k] = hi;
        g_Blo[k] = __float2bfloat16(v - __bfloat162float(hi));
    }
}
__global__ void zero_agg_kernel() {
    int i = blockIdx.x * blockDim.x + threadIdx.x;
    int stride = gridDim.x * blockDim.x;
    for (int k = i; k < NV * DD; k += stride) g_agg[k] = 0.f;
}

// ---------------- stage A1: H = relu(ea@W1+b1) -> bf16 hi/lo --------------
__global__ void __launch_bounds__(128) edge_mlp1_kernel(
    const float* __restrict__ ea, const float* __restrict__ w1,
    const float* __restrict__ b1)
{
    __shared__ float sw[EF * EH];
    __shared__ float sb[EH];
    __shared__ float sea[8 * EF];
    int t = threadIdx.x;
    for (int i = t; i < EF * EH; i += 128) sw[i] = w1[i];
    sb[t] = b1[t];
    int e0 = blockIdx.x * 8;
    for (int i = t; i < 8 * EF; i += 128) {
        int ee = e0 + i / EF;
        if (ee < NE) sea[i] = ea[(size_t)ee * EF + (i % EF)];
    }
    __syncthreads();
    #pragma unroll
    for (int q = 0; q < 8; q++) {
        int e = e0 + q;
        if (e >= NE) break;
        float acc = sb[t];
        #pragma unroll
        for (int i = 0; i < EF; i++) acc += sea[q * EF + i] * sw[i * EH + t];
        acc = fmaxf(acc, 0.f);
        __nv_bfloat16 hi = __float2bfloat16(acc);
        g_Hhi[(size_t)e * EH + t] = hi;
        g_Hlo[(size_t)e * EH + t] = __float2bfloat16(acc - __bfloat162float(hi));
    }
}

// ---------------- stage A2: We = H @ W2 + b2  (persistent mma.sync) -------
// 144 persistent CTAs (1/SM), 256 threads, 8 warps (4m x 2n).
// CTA owns bn forever: B (49KB hi+lo) loaded ONCE. A streamed through a
// 6-stage cp.async ring (16KB/stage) that never drains across 66 m-tiles.
#define OFF_BHI  0
#define OFF_BLO  24576
#define OFF_A    49152
#define SLOT_SZ  16384
#define SMEM_TOT (OFF_A + 6 * SLOT_SZ)   // 147456

__device__ __forceinline__ uint32_t smem_u32(const void* p) {
    uint32_t a;
    asm("{ .reg .u64 t; cvta.to.shared.u64 t, %1; cvt.u32.u64 %0, t; }" : "=r"(a) : "l"(p));
    return a;
}
#define CPA16(dst, src) \
    asm volatile("cp.async.cg.shared.global [%0], [%1], 16;" :: "r"(dst), "l"(src) : "memory")
#define CPA_COMMIT() asm volatile("cp.async.commit_group;" ::: "memory")
#define CPA_WAIT(n)  asm volatile("cp.async.wait_group %0;" :: "n"(n) : "memory")

#define LDSM4(r, addr) \
    asm volatile("ldmatrix.sync.aligned.m8n8.x4.shared.b16 {%0,%1,%2,%3}, [%4];" \
        : "=r"((r)[0]), "=r"((r)[1]), "=r"((r)[2]), "=r"((r)[3]) : "r"(addr))
#define LDSM4T(r, addr) \
    asm volatile("ldmatrix.sync.aligned.m8n8.x4.trans.shared.b16 {%0,%1,%2,%3}, [%4];" \
        : "=r"((r)[0]), "=r"((r)[1]), "=r"((r)[2]), "=r"((r)[3]) : "r"(addr))
#define MMA16816(d, a, b0, b1) \
    asm volatile("mma.sync.aligned.m16n8k16.row.col.f32.bf16.bf16.f32 " \
        "{%0,%1,%2,%3}, {%4,%5,%6,%7}, {%8,%9}, {%0,%1,%2,%3};" \
        : "+f"((d)[0]), "+f"((d)[1]), "+f"((d)[2]), "+f"((d)[3]) \
        : "r"((a)[0]), "r"((a)[1]), "r"((a)[2]), "r"((a)[3]), "r"(b0), "r"(b1))

__global__ void __launch_bounds__(256, 1) gemm_we_kernel(
    const float* __restrict__ be2)
{
    extern __shared__ __align__(16) char smem[];
    uint32_t sb = smem_u32(smem);

    int t = threadIdx.x;
    int lane = t & 31, wid = t >> 5;
    int warp_m = wid & 3, warp_n = wid >> 2;
    int bn = blockIdx.x / CPB;
    int strip = blockIdx.x % CPB;

    // staging indices (stage-invariant)
    const int amb = t >> 5;              // + p*8
    const int akb = (t >> 3) & 3;
    const int am8 = t & 7;

    const char* HhiB = (const char*)g_Hhi;
    const char* HloB = (const char*)g_Hlo;
    const char* BhiB = (const char*)g_Bhi;
    const char* BloB = (const char*)g_Blo;

    // ---- load B once (full K=128 x 96 cols, hi+lo): 6 chunks/thread/matrix
    #pragma unroll
    for (int p = 0; p < 6; p++) {
        int c = t + p * 256;
        int kb = c / 96;
        int rem = c - kb * 96;
        int nb = rem >> 3, k8 = rem & 7;
        size_t k = (size_t)kb * 8 + k8;
        size_t so = (k * DW + bn * BN + nb * 8) * 2;
        uint32_t doff = (uint32_t)(((kb * 12 + nb) * 8 + k8) * 16);
        CPA16(sb + OFF_BHI + doff, BhiB + so);
        CPA16(sb + OFF_BLO + doff, BloB + so);
    }
    CPA_COMMIT();

    // ---- A stage issuer: stage g covers tile jj=g>>2, k-chunk s=g&3 ----
    #define ISSUE_A(g) do {                                                     \
        int _jj = (g) >> 2;                                                     \
        int _bm = strip + CPB * _jj; if (_bm >= MT) _bm = 0;                    \
        int _k0 = ((g) & 3) * 32;                                               \
        uint32_t _base = sb + OFF_A + ((g) % 6) * SLOT_SZ;                      \
        _Pragma("unroll")                                                       \
        for (int p = 0; p < 2; p++) {                                           \
            int c = t + p * 256;                                                \
            int mb = amb + p * 8;                                               \
            size_t e = (size_t)_bm * 128 + mb * 8 + am8;                        \
            size_t so = (e * EH + _k0 + akb * 8) * 2;                           \
            uint32_t doff = (uint32_t)(((mb * 4 + akb) * 8 + am8) * 16);        \
            CPA16(_base + doff, HhiB + so);                                     \
            CPA16(_base + 8192 + doff, HloB + so);                              \
        }                                                                       \
        CPA_COMMIT();                                                           \
    } while (0)

    #pragma unroll
    for (int g = 0; g < 5; g++) ISSUE_A(g);

    // bias for this CTA's 96 cols (per-thread registers)
    int r0 = lane >> 2, c0 = (lane & 3) * 2;
    float biasx[6], biasy[6];
    #pragma unroll
    for (int g = 0; g < 6; g++) {
        int col = bn * BN + warp_n * 48 + g * 8 + c0;
        biasx[g] = be2[col]; biasy[g] = be2[col + 1];
    }

    float acc[2][6][4];
    #pragma unroll
    for (int f = 0; f < 2; f++)
        #pragma unroll
        for (int g = 0; g < 6; g++)
            #pragma unroll
            for (int i = 0; i < 4; i++) acc[f][g][i] = 0.f;

    const int total_stages = NTILE * 4;   // 264

    for (int g = 0; g < total_stages; g++) {
        int s = g & 3;
        CPA_WAIT(4);
        __syncthreads();
        if (g + 5 < total_stages) ISSUE_A(g + 5);

        uint32_t abase = sb + OFF_A + (g % 6) * SLOT_SZ;
        #pragma unroll
        for (int ks = 0; ks < 2; ks++) {
            uint32_t ahi[2][4], alo[2][4];
            #pragma unroll
            for (int f = 0; f < 2; f++) {
                int mb = warp_m * 4 + f * 2 + ((lane >> 3) & 1);
                int kb = ks * 2 + ((lane >> 4) & 1);
                uint32_t off = (uint32_t)(((mb * 4 + kb) * 8 + (lane & 7)) * 16);
                LDSM4(ahi[f], abase + off);
                LDSM4(alo[f], abase + 8192 + off);
            }
            #pragma unroll
            for (int g2 = 0; g2 < 3; g2++) {
                uint32_t bhi[4], blo[4];
                int kb = s * 4 + ks * 2 + ((lane >> 3) & 1);   // global k block
                int nb = warp_n * 6 + g2 * 2 + ((lane >> 4) & 1);
                uint32_t off = (uint32_t)(((kb * 12 + nb) * 8 + (lane & 7)) * 16);
                LDSM4T(bhi, sb + OFF_BHI + off);
                LDSM4T(blo, sb + OFF_BLO + off);
                #pragma unroll
                for (int f = 0; f < 2; f++)
                    #pragma unroll
                    for (int gg = 0; gg < 2; gg++) {
                        float* a4 = acc[f][g2 * 2 + gg];
                        MMA16816(a4, ahi[f], bhi[gg * 2], bhi[gg * 2 + 1]);  // hi*hi
                        MMA16816(a4, alo[f], bhi[gg * 2], bhi[gg * 2 + 1]);  // lo*hi
                        MMA16816(a4, ahi[f], blo[gg * 2], blo[gg * 2 + 1]);  // hi*lo
                    }
            }
        }

        if (s == 3) {
            // ---- tile epilogue: add bias, store fp32, reset acc ----
            int jj = g >> 2;
            int bm = strip + CPB * jj;
            if (bm < MT) {
                #pragma unroll
                for (int gg = 0; gg < 6; gg++) {
                    int col = bn * BN + warp_n * 48 + gg * 8 + c0;
                    #pragma unroll
                    for (int f = 0; f < 2; f++) {
                        size_t row = (size_t)bm * 128 + warp_m * 32 + f * 16 + r0;
                        float2 v0 = make_float2(acc[f][gg][0] + biasx[gg],
                                                acc[f][gg][1] + biasy[gg]);
                        float2 v1 = make_float2(acc[f][gg][2] + biasx[gg],
                                                acc[f][gg][3] + biasy[gg]);
                        *reinterpret_cast<float2*>(&g_We[row * DW + col]) = v0;
                        *reinterpret_cast<float2*>(&g_We[(row + 8) * DW + col]) = v1;
                    }
                }
            }
            #pragma unroll
            for (int f = 0; f < 2; f++)
                #pragma unroll
                for (int gg = 0; gg < 6; gg++)
                    #pragma unroll
                    for (int i = 0; i < 4; i++) acc[f][gg][i] = 0.f;
        }
    }
}

// ---------------- graph boundaries from sorted batch (int32) -------------
__global__ void graph_bounds_kernel(const int* __restrict__ batch) {
    int i = blockIdx.x * blockDim.x + threadIdx.x;
    if (i >= NV) return;
    int bi = batch[i];
    if (i == 0) {
        for (int g = 0; g <= bi; g++) g_start[g] = 0;
    } else {
        int bp = batch[i - 1];
        for (int g = bp + 1; g <= bi; g++) g_start[g] = i;
    }
    if (i == NV - 1) {
        for (int g = bi + 1; g <= NB; g++) g_start[g] = NV;
    }
}

// ---------------- message pass: agg[dst] += x[src] @ We[e] ----------------
__global__ void msg_pass_kernel(const float* __restrict__ x,
                                const int* __restrict__ ei, int addCnt)
{
    int w = (blockIdx.x * blockDim.x + threadIdx.x) >> 5;
    int lane = threadIdx.x & 31;
    if (w >= NE) return;
    int src = ei[w];
    int dst = ei[NE + w];
    float xv = (lane < DD) ? x[(size_t)src * DD + lane] : 0.f;
    float acc = 0.f;
    const float* We = g_We + (size_t)w * DW;
    #pragma unroll
    for (int i = 0; i < DD; i++) {
        float xi = __shfl_sync(0xffffffffu, xv, i);
        float wv = (lane < DD) ? We[i * DD + lane] : 0.f;
        acc += xi * wv;
    }
    if (lane < DD) atomicAdd(&g_agg[dst * DD + lane], acc);
    if (addCnt && lane == 0) atomicAdd(&g_cnt[dst], 1.f);
}

// ---------------- node update: agg/cnt + x@root + bias (opt relu) ---------
__global__ void node_update_kernel(const float* __restrict__ xin,
                                   const float* __restrict__ root,
                                   const float* __restrict__ bias,
                                   float* __restrict__ xout, int doRelu)
{
    int idx = blockIdx.x * blockDim.x + threadIdx.x;
    if (idx >= NV * DD) return;
    int v = idx / DD, j = idx % DD;
    float cnt = fmaxf(g_cnt[v], 1.f);
    float acc = g_agg[idx] / cnt + bias[j];
    const float* xr = xin + (size_t)v * DD;
    #pragma unroll
    for (int i = 0; i < DD; i++) acc += xr[i] * root[i * DD + j];
    if (doRelu) acc = fmaxf(acc, 0.f);
    xout[idx] = acc;
}

// ---------------- Set2Set: one full step (LSTM + attention) ---------------
__device__ __forceinline__ float sigm(float v) { return 1.f / (1.f + expf(-v)); }

__global__ void __launch_bounds__(128) s2s_step_kernel(
    const float* __restrict__ x2,
    const float* __restrict__ wih, const float* __restrict__ whh,
    const float* __restrict__ bih, const float* __restrict__ bhh)
{
    __shared__ float sq[2 * DD], shh[DD], scc[DD], sg[4 * DD], hn[DD];
    __shared__ float red[128];
    __shared__ float wr[4][DD];
    __shared__ float ws[4];

    int b = blockIdx.x, t = threadIdx.x;
    if (t < 2 * DD) sq[t] = g_qstar[b * 2 * DD + t];
    if (t < DD) { shh[t] = g_h[b * DD + t]; scc[t] = g_c[b * DD + t]; }
    __syncthreads();

    if (t < 4 * DD) {
        float g = bih[t] + bhh[t];
        #pragma unroll 8
        for (int u = 0; u < 2 * DD; u++) g += sq[u] * wih[t * 2 * DD + u];
        #pragma unroll 8
        for (int u = 0; u < DD; u++) g += shh[u] * whh[t * DD + u];
        sg[t] = g;
    }
    __syncthreads();

    if (t < DD) {
        float ig = sigm(sg[t]);
        float fg = sigm(sg[DD + t]);
        float gg = tanhf(sg[2 * DD + t]);
        float og = sigm(sg[3 * DD + t]);
        float cn = fg * scc[t] + ig * gg;
        float hv = og * tanhf(cn);
        g_c[b * DD + t] = cn;
        g_h[b * DD + t] = hv;
        hn[t] = hv;
    }
    __syncthreads();

    int s0 = g_start[b], s1 = g_start[b + 1];

    float lmax = -3.4e38f;
    for (int n = s0 + t; n < s1; n += 128) {
        const float* xr = x2 + (size_t)n * DD;
        float e = 0.f;
        #pragma unroll
        for (int d = 0; d < DD; d++) e += xr[d] * hn[d];
        lmax = fmaxf(lmax, e);
    }
    red[t] = lmax;
    __syncthreads();
    for (int s = 64; s > 0; s >>= 1) {
        if (t < s) red[t] = fmaxf(red[t], red[t + s]);
        __syncthreads();
    }
    float emax = red[0];
    if (!(emax > -3.0e38f)) emax = 0.f;

    float lsum = 0.f;
    float lr[DD];
    #pragma unroll
    for (int d = 0; d < DD; d++) lr[d] = 0.f;
    for (int n = s0 + t; n < s1; n += 128) {
        const float* xr = x2 + (size_t)n * DD;
        float e = 0.f;
        #pragma unroll
        for (int d = 0; d < DD; d++) e += xr[d] * hn[d];
        float ex = expf(e - emax);
        lsum += ex;
        #pragma unroll
        for (int d = 0; d < DD; d++) lr[d] += ex * xr[d];
    }
    #pragma unroll
    for (int o = 16; o > 0; o >>= 1) {
        lsum += __shfl_xor_sync(0xffffffffu, lsum, o);
        #pragma unroll
        for (int d = 0; d < DD; d++) lr[d] += __shfl_xor_sync(0xffffffffu, lr[d], o);
    }
    int wid = t >> 5, lane = t & 31;
    if (lane == 0) ws[wid] = lsum;
    if (lane < DD) wr[wid][lane] = lr[lane];
    __syncthreads();

    if (t < DD) {
        float denom = ws[0] + ws[1] + ws[2] + ws[3];
        float rsum = wr[0][t] + wr[1][t] + wr[2][t] + wr[3][t];
        float r = rsum / fmaxf(denom, 1e-16f);
        g_qstar[b * 2 * DD + t] = hn[t];
        g_qstar[b * 2 * DD + DD + t] = r;
    }
}

// ---------------- heads ----------------
__global__ void heads_kernel(const float* __restrict__ wfc2, const float* __restrict__ bfc2,
                             const float* __restrict__ wfc3, const float* __restrict__ bfc3,
                             float* __restrict__ out)
{
    int b = blockIdx.x * blockDim.x + threadIdx.x;
    if (b >= NB) return;
    const float* q = g_qstar + b * 2 * DD;
    float hid[8];
    #pragma unroll
    for (int j = 0; j < 8; j++) {
        float h = bfc2[j];
        #pragma unroll 8
        for (int u = 0; u < 2 * DD; u++) h += q[u] * wfc2[u * 8 + j];
        hid[j] = fmaxf(h, 0.f);
    }
    #pragma unroll
    for (int k = 0; k < 2; k++) {
        float o = bfc3[k];
        #pragma unroll
        for (int j = 0; j < 8; j++) o += hid[j] * wfc3[j * 2 + k];
        out[b * 2 + k] = o;
    }
}

// ---------------- launch ----------------
extern "C" void kernel_launch(void* const* d_in, const int* in_sizes, int n_in,
                              void* d_out, int out_size)
{
    const float* x        = (const float*)d_in[0];
    const float* ea       = (const float*)d_in[1];
    const float* w_e1     = (const float*)d_in[2];
    const float* b_e1     = (const float*)d_in[3];
    const float* w_e2     = (const float*)d_in[4];
    const float* b_e2     = (const float*)d_in[5];
    const float* root     = (const float*)d_in[6];
    const float* bias_c   = (const float*)d_in[7];
    const float* w_ih     = (const float*)d_in[8];
    const float* w_hh     = (const float*)d_in[9];
    const float* b_ih     = (const float*)d_in[10];
    const float* b_hh     = (const float*)d_in[11];
    const float* w_fc2    = (const float*)d_in[12];
    const float* b_fc2    = (const float*)d_in[13];
    const float* w_fc3    = (const float*)d_in[14];
    const float* b_fc3    = (const float*)d_in[15];
    const int*   ei       = (const int*)d_in[16];
    const int*   bat      = (const int*)d_in[17];
    float* out            = (float*)d_out;

    float *px1 = nullptr, *px2 = nullptr;
    cudaGetSymbolAddress((void**)&px1, g_x1);
    cudaGetSymbolAddress((void**)&px2, g_x2);
    cudaFuncSetAttribute(gemm_we_kernel,
                         cudaFuncAttributeMaxDynamicSharedMemorySize, SMEM_TOT);

    zero_all_kernel<<<1024, 256>>>(w_e2);          // also converts W2 -> bf16 hi/lo
    edge_mlp1_kernel<<<NE / 8, 128>>>(ea, w_e1, b_e1);
    graph_bounds_kernel<<<(NV + 255) / 256, 256>>>(bat);

    gemm_we_kernel<<<GEMM_CTAS, 256, SMEM_TOT>>>(b_e2);   // persistent, 1/SM

    // NNConv layer 1 (input x, relu -> g_x1)
    msg_pass_kernel<<<NE / 8, 256>>>(x, ei, 1);
    node_update_kernel<<<(NV * DD + 255) / 256, 256>>>(x, root, bias_c, px1, 1);

    // NNConv layer 2 (input g_x1 -> g_x2)
    zero_agg_kernel<<<512, 256>>>();
    msg_pass_kernel<<<NE / 8, 256>>>(px1, ei, 0);
    node_update_kernel<<<(NV * DD + 255) / 256, 256>>>(px1, root, bias_c, px2, 0);

    // Set2Set: 3 steps
    for (int s = 0; s < 3; s++)
        s2s_step_kernel<<<NB, 128>>>(px2, w_ih, w_hh, b_ih, b_hh);

    heads_kernel<<<(NB + 255) / 256, 256>>>(w_fc2, b_fc2, w_fc3, b_fc3, out);
}